// round 14
// baseline (speedup 1.0000x reference)
#include <cuda_runtime.h>
#include <cuda_fp16.h>
#include <math.h>
#include <stdint.h>

#define UNITS 1024
#define BATCH 32
#define SEQ   2048
#define MTOT  (BATCH * SEQ)     // 65536

// ------------------------- device scratch (no allocs allowed) -------------
__device__ float g_dec4[4 * BATCH * UNITS];             // k-split decoder partials
__device__ float g_scores[MTOT];                        // pre-softmax scores
__device__ __align__(1024) __half g_hid16[(size_t)MTOT * UNITS];  // hidden fp16
__device__ __align__(1024) __half g_U16[UNITS * UNITS];           // U_w^T fp16 [n,k]

// ------------------------- helpers ----------------------------------------
__device__ __forceinline__ uint32_t smem_u32(const void* p) {
    uint32_t a;
    asm("{ .reg .u64 t; cvta.to.shared.u64 t, %1; cvt.u32.u64 %0, t; }"
        : "=r"(a) : "l"(p));
    return a;
}
__device__ __forceinline__ float tanh_fast(float x) {
    float y;
    asm("tanh.approx.f32 %0, %1;" : "=f"(y) : "f"(x));
    return y;
}
__device__ __forceinline__ void ldsm_x4(uint32_t (&r)[4], uint32_t addr) {
    asm volatile("ldmatrix.sync.aligned.m8n8.x4.shared.b16 {%0,%1,%2,%3}, [%4];"
                 : "=r"(r[0]), "=r"(r[1]), "=r"(r[2]), "=r"(r[3]) : "r"(addr));
}
__device__ __forceinline__ void mma16816(float (&d)[4], const uint32_t (&a)[4],
                                         uint32_t b0, uint32_t b1) {
    asm volatile(
        "mma.sync.aligned.m16n8k16.row.col.f32.f16.f16.f32 "
        "{%0,%1,%2,%3}, {%4,%5,%6,%7}, {%8,%9}, {%0,%1,%2,%3};"
        : "+f"(d[0]), "+f"(d[1]), "+f"(d[2]), "+f"(d[3])
        : "r"(a[0]), "r"(a[1]), "r"(a[2]), "r"(a[3]), "r"(b0), "r"(b1));
}
#define CP_ASYNC16(dst, src) \
    asm volatile("cp.async.cg.shared.global [%0], [%1], 16;" :: "r"(dst), "l"(src))
#define CP_COMMIT() asm volatile("cp.async.commit_group;" ::: "memory")
#define CP_WAIT1()  asm volatile("cp.async.wait_group 1;" ::: "memory")

// ------------------------- fused preprocessing mega-kernel ----------------
// One launch, block-ID dispatch. Latency-bound blocks (decoder, cvt_U) are
// FIRST so they co-run under the BW-bound cvt_hidden wave.
//   blocks [0, 512)            : decoder k-split x4 + zero scores/ctx
//   blocks [512, 1536)         : U^T transpose+cvt (1024 32x32 tiles)
//   blocks [1536, 1536+16384)  : hidden fp32 -> fp16 (4 float4 per thread)
#define PP_DEC   512
#define PP_U     1024
#define PP_HID   16384
struct alignas(8) H4 { __half2 a, b; };

__global__ __launch_bounds__(256) void preprocess_kernel(
        const float4* __restrict__ hid4,
        const float* __restrict__ U,
        const float* __restrict__ s_prev,
        const float* __restrict__ W_w,
        const float* __restrict__ W_b,
        const float* __restrict__ U_b,
        float* __restrict__ ctx) {
    __shared__ float sbuf[33 * 32];   // union: decoder ssp[256] / cvt_U t[32][33]
    const int bid = blockIdx.x;
    const int tid = threadIdx.x;

    if (bid < PP_DEC) {
        // ---- decoder: g_dec4[kq][b*UNITS+h] = partial dot (+bias in kq=0) ----
        const int kq   = bid & 3;
        const int hblk = (bid >> 2) & 3;
        const int b    = bid >> 4;
        const int h    = hblk * 256 + tid;
        const int u0   = kq * 256;

        // fused zeroing: 512 blocks x 256 threads cover scores(64K)+ctx(32K)
        int gid = bid * 256 + tid;
        if (gid < MTOT) g_scores[gid] = 0.f;
        else if (gid < MTOT + BATCH * UNITS) ctx[gid - MTOT] = 0.f;

        sbuf[tid] = s_prev[b * UNITS + u0 + tid];
        __syncthreads();

        float a0 = 0.f, a1 = 0.f, a2 = 0.f, a3 = 0.f;
        #pragma unroll 4
        for (int u = 0; u < 256; u += 4) {
            a0 = fmaf(sbuf[u + 0], W_w[(size_t)(u0 + u + 0) * UNITS + h], a0);
            a1 = fmaf(sbuf[u + 1], W_w[(size_t)(u0 + u + 1) * UNITS + h], a1);
            a2 = fmaf(sbuf[u + 2], W_w[(size_t)(u0 + u + 2) * UNITS + h], a2);
            a3 = fmaf(sbuf[u + 3], W_w[(size_t)(u0 + u + 3) * UNITS + h], a3);
        }
        float r = (a0 + a1) + (a2 + a3);
        if (kq == 0) r += W_b[h] + U_b[h];
        g_dec4[kq * (BATCH * UNITS) + b * UNITS + h] = r;

    } else if (bid < PP_DEC + PP_U) {
        // ---- cvt_U: g_U16[n*1024+k] = (half) U[k*1024+n], one 32x32 tile ----
        const int t  = bid - PP_DEC;
        const int k0 = (t & 31) * 32;
        const int n0 = (t >> 5) * 32;
        const int tx = tid & 31;
        const int ty = tid >> 5;       // 0..7
        #pragma unroll
        for (int j = 0; j < 4; j++)
            sbuf[(ty + j * 8) * 33 + tx] =
                U[(size_t)(k0 + ty + j * 8) * UNITS + n0 + tx];
        __syncthreads();
        #pragma unroll
        for (int j = 0; j < 4; j++)
            g_U16[(size_t)(n0 + ty + j * 8) * UNITS + k0 + tx] =
                __float2half_rn(sbuf[tx * 33 + ty + j * 8]);

    } else {
        // ---- cvt_hidden: fp32 -> fp16, 4 float4 per thread (64B MLP) ----
        size_t i = (size_t)(bid - PP_DEC - PP_U) * 1024 + tid;
        float4 v0 = hid4[i];
        float4 v1 = hid4[i + 256];
        float4 v2 = hid4[i + 512];
        float4 v3 = hid4[i + 768];
        H4 o0, o1, o2, o3;
        o0.a = __floats2half2_rn(v0.x, v0.y);
        o0.b = __floats2half2_rn(v0.z, v0.w);
        o1.a = __floats2half2_rn(v1.x, v1.y);
        o1.b = __floats2half2_rn(v1.z, v1.w);
        o2.a = __floats2half2_rn(v2.x, v2.y);
        o2.b = __floats2half2_rn(v2.z, v2.w);
        o3.a = __floats2half2_rn(v3.x, v3.y);
        o3.b = __floats2half2_rn(v3.z, v3.w);
        ((H4*)g_hid16)[i] = o0;
        ((H4*)g_hid16)[i + 256] = o1;
        ((H4*)g_hid16)[i + 512] = o2;
        ((H4*)g_hid16)[i + 768] = o3;
    }
}

// ------------------------- fused HMMA score GEMM (R6 champion, frozen) ----
// C[m,n] = sum_k hid16[m,k] * U16[n,k];  score[m] += sum_n tanh(C+dec)*Vw[n]
// BM=128, BN=128, BK=32, 3-stage cp.async.
// 4 warps (2m x 2n), warp tile 64x64, 2 CTAs/SM.
#define BK       32
#define STAGES   3
#define ROWB     80                   // bytes per smem row (64 data + 16 pad)
#define T_BYTES  (128 * ROWB)         // 10240 per tile
#define STG_B    (2 * T_BYTES)        // 20480
#define SMEM_GEMM (STAGES * STG_B + 256 * 4)   // 62464

__global__ __launch_bounds__(128, 2) void score_gemm_kernel(
        const float* __restrict__ Vw) {
    extern __shared__ __align__(16) char smem[];
    float* dec_s = (float*)(smem + STAGES * STG_B);
    float* vw_s  = dec_s + 128;
    float (*sred)[2] = (float(*)[2])smem;     // aliases tiles post-loop

    const uint32_t sbase = smem_u32(smem);
    const int tid  = threadIdx.x;
    const int wid  = tid >> 5;
    const int lane = tid & 31;
    const int warp_m = wid & 1;       // 0..1  (64-row slabs)
    const int warp_n = wid >> 1;      // 0..1  (64-col slabs)

    const int n0 = blockIdx.x * 128;  // n fast-varying -> A reuse via L2
    const int m0 = blockIdx.y * 128;
    const int bidx = m0 >> 11;        // m0 / SEQ

    {   // sum the 4 decoder k-slabs
        int idx = bidx * UNITS + n0 + tid;
        dec_s[tid] = (g_dec4[idx] + g_dec4[idx + BATCH * UNITS])
                   + (g_dec4[idx + 2 * BATCH * UNITS] + g_dec4[idx + 3 * BATCH * UNITS]);
    }
    vw_s[tid]  = Vw[n0 + tid];

    const __half* gA = g_hid16 + (size_t)m0 * UNITS;
    const __half* gB = g_U16   + (size_t)n0 * UNITS;

    float acc[4][8][4] = {};

    // cp.async: 4 A-chunks + 4 B-chunks per thread per stage (128 threads)
    auto load_stage = [&](int s, int k0) {
        uint32_t aOff = sbase + (uint32_t)s * STG_B;
        uint32_t bOff = aOff + T_BYTES;
        #pragma unroll
        for (int j = 0; j < 4; j++) {
            int c = tid + j * 128;
            int r = c >> 2, k = c & 3;
            CP_ASYNC16(aOff + r * ROWB + k * 16, gA + (size_t)r * UNITS + k0 + k * 8);
            CP_ASYNC16(bOff + r * ROWB + k * 16, gB + (size_t)r * UNITS + k0 + k * 8);
        }
    };

    load_stage(0, 0);  CP_COMMIT();
    load_stage(1, BK); CP_COMMIT();

    const int lrow = lane & 15;
    const int lkb  = (lane >> 4) * 16;
    const int bg   = lane >> 3;       // 0..3 ldmatrix group
    const int blg  = lane & 7;

    int s = 0, s2 = 2;                // current stage, prefetch stage
    #pragma unroll 1
    for (int kt = 0; kt < UNITS / BK; kt++) {
        CP_WAIT1();
        __syncthreads();
        if (kt + 2 < UNITS / BK) load_stage(s2, (kt + 2) * BK);
        CP_COMMIT();

        const uint32_t aOff = sbase + (uint32_t)s * STG_B;
        const uint32_t bOff = aOff + T_BYTES;

        #pragma unroll
        for (int ks = 0; ks < 2; ks++) {
            // ---- phase 1: all fragment loads for this ks ----
            uint32_t afr[4][4];
            #pragma unroll
            for (int mt = 0; mt < 4; mt++)
                ldsm_x4(afr[mt], aOff + (warp_m * 64 + mt * 16 + lrow) * ROWB
                                      + ks * 32 + lkb);
            uint32_t bfr[8][2];
            #pragma unroll
            for (int p = 0; p < 4; p++) {
                uint32_t r[4];
                ldsm_x4(r, bOff + (warp_n * 64 + p * 16 + (bg >> 1) * 8 + blg) * ROWB
                              + ks * 32 + (bg & 1) * 16);
                bfr[2 * p][0]     = r[0]; bfr[2 * p][1]     = r[1];
                bfr[2 * p + 1][0] = r[2]; bfr[2 * p + 1][1] = r[3];
            }
            // ---- phase 2: 32 MMAs ----
            #pragma unroll
            for (int mt = 0; mt < 4; mt++)
                #pragma unroll
                for (int nt = 0; nt < 8; nt++)
                    mma16816(acc[mt][nt], afr[mt], bfr[nt][0], bfr[nt][1]);
        }
        s  = (s  == STAGES - 1) ? 0 : s + 1;
        s2 = (s2 == STAGES - 1) ? 0 : s2 + 1;
    }

    // ---- fused epilogue: tanh + Vw dot, quad-reduce, smem cross-warp ----
    float tdec[16], tvw[16];
    #pragma unroll
    for (int nt = 0; nt < 8; nt++)
        #pragma unroll
        for (int j = 0; j < 2; j++) {
            int c = warp_n * 64 + nt * 8 + (lane & 3) * 2 + j;
            tdec[nt * 2 + j] = dec_s[c];
            tvw[nt * 2 + j]  = vw_s[c];
        }

    __syncthreads();   // all warps done reading tiles; smem reusable as sred

    #pragma unroll
    for (int mt = 0; mt < 4; mt++) {
        float p0 = 0.f, p1 = 0.f;
        #pragma unroll
        for (int nt = 0; nt < 8; nt++) {
            p0 = fmaf(tanh_fast(acc[mt][nt][0] + tdec[nt * 2]),     tvw[nt * 2],     p0);
            p0 = fmaf(tanh_fast(acc[mt][nt][1] + tdec[nt * 2 + 1]), tvw[nt * 2 + 1], p0);
            p1 = fmaf(tanh_fast(acc[mt][nt][2] + tdec[nt * 2]),     tvw[nt * 2],     p1);
            p1 = fmaf(tanh_fast(acc[mt][nt][3] + tdec[nt * 2 + 1]), tvw[nt * 2 + 1], p1);
        }
        p0 += __shfl_xor_sync(0xffffffffu, p0, 1);
        p0 += __shfl_xor_sync(0xffffffffu, p0, 2);
        p1 += __shfl_xor_sync(0xffffffffu, p1, 1);
        p1 += __shfl_xor_sync(0xffffffffu, p1, 2);
        if ((lane & 3) == 0) {
            int r = warp_m * 64 + mt * 16 + (lane >> 2);
            sred[r][warp_n]     = p0;
            sred[r + 8][warp_n] = p1;
        }
    }
    __syncthreads();

    {
        float ssum = sred[tid][0] + sred[tid][1];
        atomicAdd(&g_scores[m0 + tid], ssum);
    }
}

// ------------------------- softmax (smem-cached) ---------------------------
__global__ void softmax_kernel(float* __restrict__ alpha_out) {
    __shared__ float sc_s[SEQ];
    __shared__ float red[256];
    const int b = blockIdx.x;
    const int tid = threadIdx.x;
    const float* sc = g_scores + b * SEQ;
    float* al = alpha_out + b * SEQ;

    float m = -INFINITY;
    for (int s = tid; s < SEQ; s += 256) {
        float v = sc[s];
        sc_s[s] = v;
        m = fmaxf(m, v);
    }
    red[tid] = m;
    __syncthreads();
    for (int o = 128; o > 0; o >>= 1) {
        if (tid < o) red[tid] = fmaxf(red[tid], red[tid + o]);
        __syncthreads();
    }
    m = red[0];
    __syncthreads();

    float sum = 0.f;
    for (int s = tid; s < SEQ; s += 256) {
        float e = expf(sc_s[s] - m);
        sc_s[s] = e;
        sum += e;
    }
    red[tid] = sum;
    __syncthreads();
    for (int o = 128; o > 0; o >>= 1) {
        if (tid < o) red[tid] += red[tid + o];
        __syncthreads();
    }
    float inv = 1.f / red[0];
    __syncthreads();
    for (int s = tid; s < SEQ; s += 256) al[s] = sc_s[s] * inv;
}

// ------------------------- context (fp16 hidden, 16B loads, s-split 16) ---
// Each thread owns 8 consecutive units (one uint4 of halves), 8 accumulators.
// grid (BATCH, 16), block 128.
__global__ __launch_bounds__(128) void context16_kernel(
        const float* __restrict__ alpha, float* __restrict__ ctx) {
    __shared__ float sal[128];
    const int b = blockIdx.x;
    const int s0 = blockIdx.y * 128;
    const int tid = threadIdx.x;      // 0..127, uint4 column index

    sal[tid] = alpha[b * SEQ + s0 + tid];
    __syncthreads();

    const uint4* hp = (const uint4*)g_hid16 + ((size_t)b * SEQ + s0) * 128 + tid;
    float acc[8] = {};
    #pragma unroll 4
    for (int s = 0; s < 128; s++) {
        uint4 v = hp[(size_t)s * 128];
        float a = sal[s];
        float2 f0 = __half22float2(*(__half2*)&v.x);
        float2 f1 = __half22float2(*(__half2*)&v.y);
        float2 f2 = __half22float2(*(__half2*)&v.z);
        float2 f3 = __half22float2(*(__half2*)&v.w);
        acc[0] = fmaf(a, f0.x, acc[0]); acc[1] = fmaf(a, f0.y, acc[1]);
        acc[2] = fmaf(a, f1.x, acc[2]); acc[3] = fmaf(a, f1.y, acc[3]);
        acc[4] = fmaf(a, f2.x, acc[4]); acc[5] = fmaf(a, f2.y, acc[5]);
        acc[6] = fmaf(a, f3.x, acc[6]); acc[7] = fmaf(a, f3.y, acc[7]);
    }
    #pragma unroll
    for (int j = 0; j < 8; j++)
        atomicAdd(&ctx[b * UNITS + tid * 8 + j], acc[j]);
}

// ------------------------- host launcher ----------------------------------
extern "C" void kernel_launch(void* const* d_in, const int* in_sizes, int n_in,
                              void* d_out, int out_size) {
    const float* s_prev = (const float*)d_in[0];
    const float* hidden = (const float*)d_in[1];
    const float* W_w    = (const float*)d_in[2];
    const float* W_b    = (const float*)d_in[3];
    const float* U_w    = (const float*)d_in[4];
    const float* U_b    = (const float*)d_in[5];
    const float* V_w    = (const float*)d_in[6];
    // d_in[7] = V_b: constant shift of scores, softmax-invariant -> unused.

    float* out_ctx   = (float*)d_out;                  // BATCH*UNITS
    float* out_alpha = (float*)d_out + BATCH * UNITS;  // BATCH*SEQ

    cudaFuncSetAttribute(score_gemm_kernel,
                         cudaFuncAttributeMaxDynamicSharedMemorySize, SMEM_GEMM);

    // 1. fused preprocessing: decoder + U^T cvt + hidden cvt, one launch
    preprocess_kernel<<<PP_DEC + PP_U + PP_HID, 256>>>(
        (const float4*)hidden, U_w, s_prev, W_w, W_b, U_b, out_ctx);
    // 2. fused HMMA GEMM + tanh + V reduction
    score_gemm_kernel<<<dim3(UNITS / 128, MTOT / 128), 128, SMEM_GEMM>>>(V_w);
    // 3. softmax
    softmax_kernel<<<BATCH, 256>>>(out_alpha);
    // 4. context from fp16 hidden (16B loads)
    context16_kernel<<<dim3(BATCH, 16), 128>>>(out_alpha, out_ctx);
}

// round 15
// speedup vs baseline: 1.0215x; 1.0215x over previous
#include <cuda_runtime.h>
#include <cuda_fp16.h>
#include <math.h>
#include <stdint.h>

#define UNITS 1024
#define BATCH 32
#define SEQ   2048
#define MTOT  (BATCH * SEQ)     // 65536

// ------------------------- device scratch (no allocs allowed) -------------
__device__ float g_dec4[4 * BATCH * UNITS];             // k-split decoder partials
__device__ float g_scores[MTOT];                        // pre-softmax scores
__device__ __align__(1024) __half g_hid16[(size_t)MTOT * UNITS];  // hidden fp16
__device__ __align__(1024) __half g_U16[UNITS * UNITS];           // U_w^T fp16 [n,k]

// ------------------------- helpers ----------------------------------------
__device__ __forceinline__ uint32_t smem_u32(const void* p) {
    uint32_t a;
    asm("{ .reg .u64 t; cvta.to.shared.u64 t, %1; cvt.u32.u64 %0, t; }"
        : "=r"(a) : "l"(p));
    return a;
}
__device__ __forceinline__ float tanh_fast(float x) {
    float y;
    asm("tanh.approx.f32 %0, %1;" : "=f"(y) : "f"(x));
    return y;
}
__device__ __forceinline__ void ldsm_x4(uint32_t (&r)[4], uint32_t addr) {
    asm volatile("ldmatrix.sync.aligned.m8n8.x4.shared.b16 {%0,%1,%2,%3}, [%4];"
                 : "=r"(r[0]), "=r"(r[1]), "=r"(r[2]), "=r"(r[3]) : "r"(addr));
}
__device__ __forceinline__ void mma16816(float (&d)[4], const uint32_t (&a)[4],
                                         uint32_t b0, uint32_t b1) {
    asm volatile(
        "mma.sync.aligned.m16n8k16.row.col.f32.f16.f16.f32 "
        "{%0,%1,%2,%3}, {%4,%5,%6,%7}, {%8,%9}, {%0,%1,%2,%3};"
        : "+f"(d[0]), "+f"(d[1]), "+f"(d[2]), "+f"(d[3])
        : "r"(a[0]), "r"(a[1]), "r"(a[2]), "r"(a[3]), "r"(b0), "r"(b1));
}
#define CP_ASYNC16(dst, src) \
    asm volatile("cp.async.cg.shared.global [%0], [%1], 16;" :: "r"(dst), "l"(src))
#define CP_COMMIT() asm volatile("cp.async.commit_group;" ::: "memory")
#define CP_WAIT1()  asm volatile("cp.async.wait_group 1;" ::: "memory")

// ------------------------- fused preprocessing mega-kernel ----------------
// One launch, block-ID dispatch. Latency-bound blocks (decoder, cvt_U) are
// FIRST so they co-run under the BW-bound cvt_hidden wave.
//   blocks [0, 512)            : decoder k-split x4 + zero scores/ctx
//   blocks [512, 1536)         : U^T transpose+cvt (1024 32x32 tiles)
//   blocks [1536, 1536+32768)  : hidden fp32 -> fp16 (2 float4 per thread)
#define PP_DEC   512
#define PP_U     1024
#define PP_HID   32768
struct alignas(8) H4 { __half2 a, b; };

__global__ __launch_bounds__(256) void preprocess_kernel(
        const float4* __restrict__ hid4,
        const float* __restrict__ U,
        const float* __restrict__ s_prev,
        const float* __restrict__ W_w,
        const float* __restrict__ W_b,
        const float* __restrict__ U_b,
        float* __restrict__ ctx) {
    __shared__ float sbuf[33 * 32];   // union: decoder ssp[256] / cvt_U t[32][33]
    const int bid = blockIdx.x;
    const int tid = threadIdx.x;

    if (bid < PP_DEC) {
        // ---- decoder: g_dec4[kq][b*UNITS+h] = partial dot (+bias in kq=0) ----
        const int kq   = bid & 3;
        const int hblk = (bid >> 2) & 3;
        const int b    = bid >> 4;
        const int h    = hblk * 256 + tid;
        const int u0   = kq * 256;

        // fused zeroing: 512 blocks x 256 threads cover scores(64K)+ctx(32K)
        int gid = bid * 256 + tid;
        if (gid < MTOT) g_scores[gid] = 0.f;
        else if (gid < MTOT + BATCH * UNITS) ctx[gid - MTOT] = 0.f;

        sbuf[tid] = s_prev[b * UNITS + u0 + tid];
        __syncthreads();

        float a0 = 0.f, a1 = 0.f, a2 = 0.f, a3 = 0.f;
        #pragma unroll 4
        for (int u = 0; u < 256; u += 4) {
            a0 = fmaf(sbuf[u + 0], W_w[(size_t)(u0 + u + 0) * UNITS + h], a0);
            a1 = fmaf(sbuf[u + 1], W_w[(size_t)(u0 + u + 1) * UNITS + h], a1);
            a2 = fmaf(sbuf[u + 2], W_w[(size_t)(u0 + u + 2) * UNITS + h], a2);
            a3 = fmaf(sbuf[u + 3], W_w[(size_t)(u0 + u + 3) * UNITS + h], a3);
        }
        float r = (a0 + a1) + (a2 + a3);
        if (kq == 0) r += W_b[h] + U_b[h];
        g_dec4[kq * (BATCH * UNITS) + b * UNITS + h] = r;

    } else if (bid < PP_DEC + PP_U) {
        // ---- cvt_U: g_U16[n*1024+k] = (half) U[k*1024+n], one 32x32 tile ----
        const int t  = bid - PP_DEC;
        const int k0 = (t & 31) * 32;
        const int n0 = (t >> 5) * 32;
        const int tx = tid & 31;
        const int ty = tid >> 5;       // 0..7
        #pragma unroll
        for (int j = 0; j < 4; j++)
            sbuf[(ty + j * 8) * 33 + tx] =
                U[(size_t)(k0 + ty + j * 8) * UNITS + n0 + tx];
        __syncthreads();
        #pragma unroll
        for (int j = 0; j < 4; j++)
            g_U16[(size_t)(n0 + ty + j * 8) * UNITS + k0 + tx] =
                __float2half_rn(sbuf[tx * 33 + ty + j * 8]);

    } else {
        // ---- cvt_hidden: fp32 -> fp16, 2 float4 per thread ----
        size_t i = (size_t)(bid - PP_DEC - PP_U) * 512 + tid;
        float4 v0 = hid4[i];
        float4 v1 = hid4[i + 256];
        H4 o0, o1;
        o0.a = __floats2half2_rn(v0.x, v0.y);
        o0.b = __floats2half2_rn(v0.z, v0.w);
        o1.a = __floats2half2_rn(v1.x, v1.y);
        o1.b = __floats2half2_rn(v1.z, v1.w);
        ((H4*)g_hid16)[i] = o0;
        ((H4*)g_hid16)[i + 256] = o1;
    }
}

// ------------------------- fused HMMA score GEMM (R6 champion, frozen) ----
// C[m,n] = sum_k hid16[m,k] * U16[n,k];  score[m] += sum_n tanh(C+dec)*Vw[n]
// BM=128, BN=128, BK=32, 3-stage cp.async.
// 4 warps (2m x 2n), warp tile 64x64, 2 CTAs/SM.
#define BK       32
#define STAGES   3
#define ROWB     80                   // bytes per smem row (64 data + 16 pad)
#define T_BYTES  (128 * ROWB)         // 10240 per tile
#define STG_B    (2 * T_BYTES)        // 20480
#define SMEM_GEMM (STAGES * STG_B + 256 * 4)   // 62464

__global__ __launch_bounds__(128, 2) void score_gemm_kernel(
        const float* __restrict__ Vw) {
    extern __shared__ __align__(16) char smem[];
    float* dec_s = (float*)(smem + STAGES * STG_B);
    float* vw_s  = dec_s + 128;
    float (*sred)[2] = (float(*)[2])smem;     // aliases tiles post-loop

    const uint32_t sbase = smem_u32(smem);
    const int tid  = threadIdx.x;
    const int wid  = tid >> 5;
    const int lane = tid & 31;
    const int warp_m = wid & 1;       // 0..1  (64-row slabs)
    const int warp_n = wid >> 1;      // 0..1  (64-col slabs)

    const int n0 = blockIdx.x * 128;  // n fast-varying -> A reuse via L2
    const int m0 = blockIdx.y * 128;
    const int bidx = m0 >> 11;        // m0 / SEQ

    {   // sum the 4 decoder k-slabs
        int idx = bidx * UNITS + n0 + tid;
        dec_s[tid] = (g_dec4[idx] + g_dec4[idx + BATCH * UNITS])
                   + (g_dec4[idx + 2 * BATCH * UNITS] + g_dec4[idx + 3 * BATCH * UNITS]);
    }
    vw_s[tid]  = Vw[n0 + tid];

    const __half* gA = g_hid16 + (size_t)m0 * UNITS;
    const __half* gB = g_U16   + (size_t)n0 * UNITS;

    float acc[4][8][4] = {};

    // cp.async: 4 A-chunks + 4 B-chunks per thread per stage (128 threads)
    auto load_stage = [&](int s, int k0) {
        uint32_t aOff = sbase + (uint32_t)s * STG_B;
        uint32_t bOff = aOff + T_BYTES;
        #pragma unroll
        for (int j = 0; j < 4; j++) {
            int c = tid + j * 128;
            int r = c >> 2, k = c & 3;
            CP_ASYNC16(aOff + r * ROWB + k * 16, gA + (size_t)r * UNITS + k0 + k * 8);
            CP_ASYNC16(bOff + r * ROWB + k * 16, gB + (size_t)r * UNITS + k0 + k * 8);
        }
    };

    load_stage(0, 0);  CP_COMMIT();
    load_stage(1, BK); CP_COMMIT();

    const int lrow = lane & 15;
    const int lkb  = (lane >> 4) * 16;
    const int bg   = lane >> 3;       // 0..3 ldmatrix group
    const int blg  = lane & 7;

    int s = 0, s2 = 2;                // current stage, prefetch stage
    #pragma unroll 1
    for (int kt = 0; kt < UNITS / BK; kt++) {
        CP_WAIT1();
        __syncthreads();
        if (kt + 2 < UNITS / BK) load_stage(s2, (kt + 2) * BK);
        CP_COMMIT();

        const uint32_t aOff = sbase + (uint32_t)s * STG_B;
        const uint32_t bOff = aOff + T_BYTES;

        #pragma unroll
        for (int ks = 0; ks < 2; ks++) {
            // ---- phase 1: all fragment loads for this ks ----
            uint32_t afr[4][4];
            #pragma unroll
            for (int mt = 0; mt < 4; mt++)
                ldsm_x4(afr[mt], aOff + (warp_m * 64 + mt * 16 + lrow) * ROWB
                                      + ks * 32 + lkb);
            uint32_t bfr[8][2];
            #pragma unroll
            for (int p = 0; p < 4; p++) {
                uint32_t r[4];
                ldsm_x4(r, bOff + (warp_n * 64 + p * 16 + (bg >> 1) * 8 + blg) * ROWB
                              + ks * 32 + (bg & 1) * 16);
                bfr[2 * p][0]     = r[0]; bfr[2 * p][1]     = r[1];
                bfr[2 * p + 1][0] = r[2]; bfr[2 * p + 1][1] = r[3];
            }
            // ---- phase 2: 32 MMAs ----
            #pragma unroll
            for (int mt = 0; mt < 4; mt++)
                #pragma unroll
                for (int nt = 0; nt < 8; nt++)
                    mma16816(acc[mt][nt], afr[mt], bfr[nt][0], bfr[nt][1]);
        }
        s  = (s  == STAGES - 1) ? 0 : s + 1;
        s2 = (s2 == STAGES - 1) ? 0 : s2 + 1;
    }

    // ---- fused epilogue: tanh + Vw dot, quad-reduce, smem cross-warp ----
    float tdec[16], tvw[16];
    #pragma unroll
    for (int nt = 0; nt < 8; nt++)
        #pragma unroll
        for (int j = 0; j < 2; j++) {
            int c = warp_n * 64 + nt * 8 + (lane & 3) * 2 + j;
            tdec[nt * 2 + j] = dec_s[c];
            tvw[nt * 2 + j]  = vw_s[c];
        }

    __syncthreads();   // all warps done reading tiles; smem reusable as sred

    #pragma unroll
    for (int mt = 0; mt < 4; mt++) {
        float p0 = 0.f, p1 = 0.f;
        #pragma unroll
        for (int nt = 0; nt < 8; nt++) {
            p0 = fmaf(tanh_fast(acc[mt][nt][0] + tdec[nt * 2]),     tvw[nt * 2],     p0);
            p0 = fmaf(tanh_fast(acc[mt][nt][1] + tdec[nt * 2 + 1]), tvw[nt * 2 + 1], p0);
            p1 = fmaf(tanh_fast(acc[mt][nt][2] + tdec[nt * 2]),     tvw[nt * 2],     p1);
            p1 = fmaf(tanh_fast(acc[mt][nt][3] + tdec[nt * 2 + 1]), tvw[nt * 2 + 1], p1);
        }
        p0 += __shfl_xor_sync(0xffffffffu, p0, 1);
        p0 += __shfl_xor_sync(0xffffffffu, p0, 2);
        p1 += __shfl_xor_sync(0xffffffffu, p1, 1);
        p1 += __shfl_xor_sync(0xffffffffu, p1, 2);
        if ((lane & 3) == 0) {
            int r = warp_m * 64 + mt * 16 + (lane >> 2);
            sred[r][warp_n]     = p0;
            sred[r + 8][warp_n] = p1;
        }
    }
    __syncthreads();

    {
        float ssum = sred[tid][0] + sred[tid][1];
        atomicAdd(&g_scores[m0 + tid], ssum);
    }
}

// ------------------------- softmax (smem-cached) ---------------------------
__global__ void softmax_kernel(float* __restrict__ alpha_out) {
    __shared__ float sc_s[SEQ];
    __shared__ float red[256];
    const int b = blockIdx.x;
    const int tid = threadIdx.x;
    const float* sc = g_scores + b * SEQ;
    float* al = alpha_out + b * SEQ;

    float m = -INFINITY;
    for (int s = tid; s < SEQ; s += 256) {
        float v = sc[s];
        sc_s[s] = v;
        m = fmaxf(m, v);
    }
    red[tid] = m;
    __syncthreads();
    for (int o = 128; o > 0; o >>= 1) {
        if (tid < o) red[tid] = fmaxf(red[tid], red[tid + o]);
        __syncthreads();
    }
    m = red[0];
    __syncthreads();

    float sum = 0.f;
    for (int s = tid; s < SEQ; s += 256) {
        float e = expf(sc_s[s] - m);
        sc_s[s] = e;
        sum += e;
    }
    red[tid] = sum;
    __syncthreads();
    for (int o = 128; o > 0; o >>= 1) {
        if (tid < o) red[tid] += red[tid + o];
        __syncthreads();
    }
    float inv = 1.f / red[0];
    __syncthreads();
    for (int s = tid; s < SEQ; s += 256) al[s] = sc_s[s] * inv;
}

// ------------------------- context: 16B loads, 256 thr, 2-way s-group -----
// grid (BATCH, 16), block 256. col = tid&127 (uint4 column), sgrp = tid>>7
// splits the 128-row slice into 2x64. sgroups combine in smem -> 1 atomic.
__global__ __launch_bounds__(256) void context16_kernel(
        const float* __restrict__ alpha, float* __restrict__ ctx) {
    __shared__ float sal[128];
    __shared__ float sred[128][8];
    const int b = blockIdx.x;
    const int s0 = blockIdx.y * 128;
    const int tid = threadIdx.x;
    const int col = tid & 127;        // uint4 column index
    const int sgrp = tid >> 7;        // 0..1

    if (tid < 128) sal[tid] = alpha[b * SEQ + s0 + tid];
    __syncthreads();

    const uint4* hp = (const uint4*)g_hid16
                    + ((size_t)b * SEQ + s0 + sgrp * 64) * 128 + col;
    const float* sa = sal + sgrp * 64;
    float acc[8] = {};
    #pragma unroll 4
    for (int s = 0; s < 64; s++) {
        uint4 v = hp[(size_t)s * 128];
        float a = sa[s];
        float2 f0 = __half22float2(*(__half2*)&v.x);
        float2 f1 = __half22float2(*(__half2*)&v.y);
        float2 f2 = __half22float2(*(__half2*)&v.z);
        float2 f3 = __half22float2(*(__half2*)&v.w);
        acc[0] = fmaf(a, f0.x, acc[0]); acc[1] = fmaf(a, f0.y, acc[1]);
        acc[2] = fmaf(a, f1.x, acc[2]); acc[3] = fmaf(a, f1.y, acc[3]);
        acc[4] = fmaf(a, f2.x, acc[4]); acc[5] = fmaf(a, f2.y, acc[5]);
        acc[6] = fmaf(a, f3.x, acc[6]); acc[7] = fmaf(a, f3.y, acc[7]);
    }

    if (sgrp == 1) {
        #pragma unroll
        for (int j = 0; j < 8; j++) sred[col][j] = acc[j];
    }
    __syncthreads();
    if (sgrp == 0) {
        #pragma unroll
        for (int j = 0; j < 8; j++)
            atomicAdd(&ctx[b * UNITS + col * 8 + j], acc[j] + sred[col][j]);
    }
}

// ------------------------- host launcher ----------------------------------
extern "C" void kernel_launch(void* const* d_in, const int* in_sizes, int n_in,
                              void* d_out, int out_size) {
    const float* s_prev = (const float*)d_in[0];
    const float* hidden = (const float*)d_in[1];
    const float* W_w    = (const float*)d_in[2];
    const float* W_b    = (const float*)d_in[3];
    const float* U_w    = (const float*)d_in[4];
    const float* U_b    = (const float*)d_in[5];
    const float* V_w    = (const float*)d_in[6];
    // d_in[7] = V_b: constant shift of scores, softmax-invariant -> unused.

    float* out_ctx   = (float*)d_out;                  // BATCH*UNITS
    float* out_alpha = (float*)d_out + BATCH * UNITS;  // BATCH*SEQ

    cudaFuncSetAttribute(score_gemm_kernel,
                         cudaFuncAttributeMaxDynamicSharedMemorySize, SMEM_GEMM);

    // 1. fused preprocessing: decoder + U^T cvt + hidden cvt, one launch
    preprocess_kernel<<<PP_DEC + PP_U + PP_HID, 256>>>(
        (const float4*)hidden, U_w, s_prev, W_w, W_b, U_b, out_ctx);
    // 2. fused HMMA GEMM + tanh + V reduction
    score_gemm_kernel<<<dim3(UNITS / 128, MTOT / 128), 128, SMEM_GEMM>>>(V_w);
    // 3. softmax
    softmax_kernel<<<BATCH, 256>>>(out_alpha);
    // 4. context from fp16 hidden (16B loads, 256 threads)
    context16_kernel<<<dim3(BATCH, 16), 256>>>(out_alpha, out_ctx);
}

// round 16
// speedup vs baseline: 1.0255x; 1.0039x over previous
#include <cuda_runtime.h>
#include <cuda_fp16.h>
#include <math.h>
#include <stdint.h>

#define UNITS 1024
#define BATCH 32
#define SEQ   2048
#define MTOT  (BATCH * SEQ)     // 65536

// ------------------------- device scratch (no allocs allowed) -------------
__device__ float g_dec4[4 * BATCH * UNITS];             // k-split decoder partials
__device__ float g_scores[MTOT];                        // pre-softmax scores
__device__ __align__(1024) __half g_hid16[(size_t)MTOT * UNITS];  // hidden fp16
__device__ __align__(1024) __half g_U16[UNITS * UNITS];           // U_w^T fp16 [n,k]

// ------------------------- helpers ----------------------------------------
__device__ __forceinline__ uint32_t smem_u32(const void* p) {
    uint32_t a;
    asm("{ .reg .u64 t; cvta.to.shared.u64 t, %1; cvt.u32.u64 %0, t; }"
        : "=r"(a) : "l"(p));
    return a;
}
__device__ __forceinline__ float tanh_fast(float x) {
    float y;
    asm("tanh.approx.f32 %0, %1;" : "=f"(y) : "f"(x));
    return y;
}
__device__ __forceinline__ void ldsm_x4(uint32_t (&r)[4], uint32_t addr) {
    asm volatile("ldmatrix.sync.aligned.m8n8.x4.shared.b16 {%0,%1,%2,%3}, [%4];"
                 : "=r"(r[0]), "=r"(r[1]), "=r"(r[2]), "=r"(r[3]) : "r"(addr));
}
__device__ __forceinline__ void mma16816(float (&d)[4], const uint32_t (&a)[4],
                                         uint32_t b0, uint32_t b1) {
    asm volatile(
        "mma.sync.aligned.m16n8k16.row.col.f32.f16.f16.f32 "
        "{%0,%1,%2,%3}, {%4,%5,%6,%7}, {%8,%9}, {%0,%1,%2,%3};"
        : "+f"(d[0]), "+f"(d[1]), "+f"(d[2]), "+f"(d[3])
        : "r"(a[0]), "r"(a[1]), "r"(a[2]), "r"(a[3]), "r"(b0), "r"(b1));
}
#define CP_ASYNC16(dst, src) \
    asm volatile("cp.async.cg.shared.global [%0], [%1], 16;" :: "r"(dst), "l"(src))
#define CP_COMMIT() asm volatile("cp.async.commit_group;" ::: "memory")
#define CP_WAIT1()  asm volatile("cp.async.wait_group 1;" ::: "memory")

// ------------------------- fused preprocessing mega-kernel ----------------
// One launch, block-ID dispatch. Latency-bound blocks (decoder, cvt_U) are
// FIRST so they co-run under the BW-bound cvt_hidden wave.
//   blocks [0, 512)            : decoder k-split x4 + zero scores/ctx
//   blocks [512, 1536)         : U^T transpose+cvt (1024 32x32 tiles)
//   blocks [1536, 1536+32768)  : hidden fp32 -> fp16 (2 float4 per thread)
#define PP_DEC   512
#define PP_U     1024
#define PP_HID   32768
struct alignas(8) H4 { __half2 a, b; };

__global__ __launch_bounds__(256) void preprocess_kernel(
        const float4* __restrict__ hid4,
        const float* __restrict__ U,
        const float* __restrict__ s_prev,
        const float* __restrict__ W_w,
        const float* __restrict__ W_b,
        const float* __restrict__ U_b,
        float* __restrict__ ctx) {
    __shared__ float sbuf[33 * 32];   // union: decoder ssp[256] / cvt_U t[32][33]
    const int bid = blockIdx.x;
    const int tid = threadIdx.x;

    if (bid < PP_DEC) {
        // ---- decoder: g_dec4[kq][b*UNITS+h] = partial dot (+bias in kq=0) ----
        const int kq   = bid & 3;
        const int hblk = (bid >> 2) & 3;
        const int b    = bid >> 4;
        const int h    = hblk * 256 + tid;
        const int u0   = kq * 256;

        // fused zeroing: 512 blocks x 256 threads cover scores(64K)+ctx(32K)
        int gid = bid * 256 + tid;
        if (gid < MTOT) g_scores[gid] = 0.f;
        else if (gid < MTOT + BATCH * UNITS) ctx[gid - MTOT] = 0.f;

        sbuf[tid] = s_prev[b * UNITS + u0 + tid];
        __syncthreads();

        float a0 = 0.f, a1 = 0.f, a2 = 0.f, a3 = 0.f;
        #pragma unroll 4
        for (int u = 0; u < 256; u += 4) {
            a0 = fmaf(sbuf[u + 0], W_w[(size_t)(u0 + u + 0) * UNITS + h], a0);
            a1 = fmaf(sbuf[u + 1], W_w[(size_t)(u0 + u + 1) * UNITS + h], a1);
            a2 = fmaf(sbuf[u + 2], W_w[(size_t)(u0 + u + 2) * UNITS + h], a2);
            a3 = fmaf(sbuf[u + 3], W_w[(size_t)(u0 + u + 3) * UNITS + h], a3);
        }
        float r = (a0 + a1) + (a2 + a3);
        if (kq == 0) r += W_b[h] + U_b[h];
        g_dec4[kq * (BATCH * UNITS) + b * UNITS + h] = r;

    } else if (bid < PP_DEC + PP_U) {
        // ---- cvt_U: g_U16[n*1024+k] = (half) U[k*1024+n], one 32x32 tile ----
        const int t  = bid - PP_DEC;
        const int k0 = (t & 31) * 32;
        const int n0 = (t >> 5) * 32;
        const int tx = tid & 31;
        const int ty = tid >> 5;       // 0..7
        #pragma unroll
        for (int j = 0; j < 4; j++)
            sbuf[(ty + j * 8) * 33 + tx] =
                U[(size_t)(k0 + ty + j * 8) * UNITS + n0 + tx];
        __syncthreads();
        #pragma unroll
        for (int j = 0; j < 4; j++)
            g_U16[(size_t)(n0 + ty + j * 8) * UNITS + k0 + tx] =
                __float2half_rn(sbuf[tx * 33 + ty + j * 8]);

    } else {
        // ---- cvt_hidden: fp32 -> fp16, 2 float4 per thread ----
        size_t i = (size_t)(bid - PP_DEC - PP_U) * 512 + tid;
        float4 v0 = hid4[i];
        float4 v1 = hid4[i + 256];
        H4 o0, o1;
        o0.a = __floats2half2_rn(v0.x, v0.y);
        o0.b = __floats2half2_rn(v0.z, v0.w);
        o1.a = __floats2half2_rn(v1.x, v1.y);
        o1.b = __floats2half2_rn(v1.z, v1.w);
        ((H4*)g_hid16)[i] = o0;
        ((H4*)g_hid16)[i + 256] = o1;
    }
}

// ------------------------- fused HMMA score GEMM (R6 champion, frozen) ----
// C[m,n] = sum_k hid16[m,k] * U16[n,k];  score[m] += sum_n tanh(C+dec)*Vw[n]
// BM=128, BN=128, BK=32, 3-stage cp.async.
// 4 warps (2m x 2n), warp tile 64x64, 2 CTAs/SM.
#define BK       32
#define STAGES   3
#define ROWB     80                   // bytes per smem row (64 data + 16 pad)
#define T_BYTES  (128 * ROWB)         // 10240 per tile
#define STG_B    (2 * T_BYTES)        // 20480
#define SMEM_GEMM (STAGES * STG_B + 256 * 4)   // 62464

__global__ __launch_bounds__(128, 2) void score_gemm_kernel(
        const float* __restrict__ Vw) {
    extern __shared__ __align__(16) char smem[];
    float* dec_s = (float*)(smem + STAGES * STG_B);
    float* vw_s  = dec_s + 128;
    float (*sred)[2] = (float(*)[2])smem;     // aliases tiles post-loop

    const uint32_t sbase = smem_u32(smem);
    const int tid  = threadIdx.x;
    const int wid  = tid >> 5;
    const int lane = tid & 31;
    const int warp_m = wid & 1;       // 0..1  (64-row slabs)
    const int warp_n = wid >> 1;      // 0..1  (64-col slabs)

    const int n0 = blockIdx.x * 128;  // n fast-varying -> A reuse via L2
    const int m0 = blockIdx.y * 128;
    const int bidx = m0 >> 11;        // m0 / SEQ

    {   // sum the 4 decoder k-slabs
        int idx = bidx * UNITS + n0 + tid;
        dec_s[tid] = (g_dec4[idx] + g_dec4[idx + BATCH * UNITS])
                   + (g_dec4[idx + 2 * BATCH * UNITS] + g_dec4[idx + 3 * BATCH * UNITS]);
    }
    vw_s[tid]  = Vw[n0 + tid];

    const __half* gA = g_hid16 + (size_t)m0 * UNITS;
    const __half* gB = g_U16   + (size_t)n0 * UNITS;

    float acc[4][8][4] = {};

    // cp.async: 4 A-chunks + 4 B-chunks per thread per stage (128 threads)
    auto load_stage = [&](int s, int k0) {
        uint32_t aOff = sbase + (uint32_t)s * STG_B;
        uint32_t bOff = aOff + T_BYTES;
        #pragma unroll
        for (int j = 0; j < 4; j++) {
            int c = tid + j * 128;
            int r = c >> 2, k = c & 3;
            CP_ASYNC16(aOff + r * ROWB + k * 16, gA + (size_t)r * UNITS + k0 + k * 8);
            CP_ASYNC16(bOff + r * ROWB + k * 16, gB + (size_t)r * UNITS + k0 + k * 8);
        }
    };

    load_stage(0, 0);  CP_COMMIT();
    load_stage(1, BK); CP_COMMIT();

    const int lrow = lane & 15;
    const int lkb  = (lane >> 4) * 16;
    const int bg   = lane >> 3;       // 0..3 ldmatrix group
    const int blg  = lane & 7;

    int s = 0, s2 = 2;                // current stage, prefetch stage
    #pragma unroll 1
    for (int kt = 0; kt < UNITS / BK; kt++) {
        CP_WAIT1();
        __syncthreads();
        if (kt + 2 < UNITS / BK) load_stage(s2, (kt + 2) * BK);
        CP_COMMIT();

        const uint32_t aOff = sbase + (uint32_t)s * STG_B;
        const uint32_t bOff = aOff + T_BYTES;

        #pragma unroll
        for (int ks = 0; ks < 2; ks++) {
            // ---- phase 1: all fragment loads for this ks ----
            uint32_t afr[4][4];
            #pragma unroll
            for (int mt = 0; mt < 4; mt++)
                ldsm_x4(afr[mt], aOff + (warp_m * 64 + mt * 16 + lrow) * ROWB
                                      + ks * 32 + lkb);
            uint32_t bfr[8][2];
            #pragma unroll
            for (int p = 0; p < 4; p++) {
                uint32_t r[4];
                ldsm_x4(r, bOff + (warp_n * 64 + p * 16 + (bg >> 1) * 8 + blg) * ROWB
                              + ks * 32 + (bg & 1) * 16);
                bfr[2 * p][0]     = r[0]; bfr[2 * p][1]     = r[1];
                bfr[2 * p + 1][0] = r[2]; bfr[2 * p + 1][1] = r[3];
            }
            // ---- phase 2: 32 MMAs ----
            #pragma unroll
            for (int mt = 0; mt < 4; mt++)
                #pragma unroll
                for (int nt = 0; nt < 8; nt++)
                    mma16816(acc[mt][nt], afr[mt], bfr[nt][0], bfr[nt][1]);
        }
        s  = (s  == STAGES - 1) ? 0 : s + 1;
        s2 = (s2 == STAGES - 1) ? 0 : s2 + 1;
    }

    // ---- fused epilogue: tanh + Vw dot, quad-reduce, smem cross-warp ----
    float tdec[16], tvw[16];
    #pragma unroll
    for (int nt = 0; nt < 8; nt++)
        #pragma unroll
        for (int j = 0; j < 2; j++) {
            int c = warp_n * 64 + nt * 8 + (lane & 3) * 2 + j;
            tdec[nt * 2 + j] = dec_s[c];
            tvw[nt * 2 + j]  = vw_s[c];
        }

    __syncthreads();   // all warps done reading tiles; smem reusable as sred

    #pragma unroll
    for (int mt = 0; mt < 4; mt++) {
        float p0 = 0.f, p1 = 0.f;
        #pragma unroll
        for (int nt = 0; nt < 8; nt++) {
            p0 = fmaf(tanh_fast(acc[mt][nt][0] + tdec[nt * 2]),     tvw[nt * 2],     p0);
            p0 = fmaf(tanh_fast(acc[mt][nt][1] + tdec[nt * 2 + 1]), tvw[nt * 2 + 1], p0);
            p1 = fmaf(tanh_fast(acc[mt][nt][2] + tdec[nt * 2]),     tvw[nt * 2],     p1);
            p1 = fmaf(tanh_fast(acc[mt][nt][3] + tdec[nt * 2 + 1]), tvw[nt * 2 + 1], p1);
        }
        p0 += __shfl_xor_sync(0xffffffffu, p0, 1);
        p0 += __shfl_xor_sync(0xffffffffu, p0, 2);
        p1 += __shfl_xor_sync(0xffffffffu, p1, 1);
        p1 += __shfl_xor_sync(0xffffffffu, p1, 2);
        if ((lane & 3) == 0) {
            int r = warp_m * 64 + mt * 16 + (lane >> 2);
            sred[r][warp_n]     = p0;
            sred[r + 8][warp_n] = p1;
        }
    }
    __syncthreads();

    {
        float ssum = sred[tid][0] + sred[tid][1];
        atomicAdd(&g_scores[m0 + tid], ssum);
    }
}

// ------------------------- softmax (smem-cached) ---------------------------
__global__ void softmax_kernel(float* __restrict__ alpha_out) {
    __shared__ float sc_s[SEQ];
    __shared__ float red[256];
    const int b = blockIdx.x;
    const int tid = threadIdx.x;
    const float* sc = g_scores + b * SEQ;
    float* al = alpha_out + b * SEQ;

    float m = -INFINITY;
    for (int s = tid; s < SEQ; s += 256) {
        float v = sc[s];
        sc_s[s] = v;
        m = fmaxf(m, v);
    }
    red[tid] = m;
    __syncthreads();
    for (int o = 128; o > 0; o >>= 1) {
        if (tid < o) red[tid] = fmaxf(red[tid], red[tid + o]);
        __syncthreads();
    }
    m = red[0];
    __syncthreads();

    float sum = 0.f;
    for (int s = tid; s < SEQ; s += 256) {
        float e = expf(sc_s[s] - m);
        sc_s[s] = e;
        sum += e;
    }
    red[tid] = sum;
    __syncthreads();
    for (int o = 128; o > 0; o >>= 1) {
        if (tid < o) red[tid] += red[tid + o];
        __syncthreads();
    }
    float inv = 1.f / red[0];
    __syncthreads();
    for (int s = tid; s < SEQ; s += 256) al[s] = sc_s[s] * inv;
}

// ------------------------- context: 16B loads, s-split 32, 2-way s-group --
// grid (BATCH, 32), block 256. col = tid&127 (uint4 column), sgrp = tid>>7
// splits the 64-row slice into 2x32. sgroups combine in smem -> 1 atomic.
__global__ __launch_bounds__(256) void context16_kernel(
        const float* __restrict__ alpha, float* __restrict__ ctx) {
    __shared__ float sal[64];
    __shared__ float sred[128][8];
    const int b = blockIdx.x;
    const int s0 = blockIdx.y * 64;
    const int tid = threadIdx.x;
    const int col = tid & 127;        // uint4 column index
    const int sgrp = tid >> 7;        // 0..1

    if (tid < 64) sal[tid] = alpha[b * SEQ + s0 + tid];
    __syncthreads();

    const uint4* hp = (const uint4*)g_hid16
                    + ((size_t)b * SEQ + s0 + sgrp * 32) * 128 + col;
    const float* sa = sal + sgrp * 32;
    float acc[8] = {};
    #pragma unroll 4
    for (int s = 0; s < 32; s++) {
        uint4 v = hp[(size_t)s * 128];
        float a = sa[s];
        float2 f0 = __half22float2(*(__half2*)&v.x);
        float2 f1 = __half22float2(*(__half2*)&v.y);
        float2 f2 = __half22float2(*(__half2*)&v.z);
        float2 f3 = __half22float2(*(__half2*)&v.w);
        acc[0] = fmaf(a, f0.x, acc[0]); acc[1] = fmaf(a, f0.y, acc[1]);
        acc[2] = fmaf(a, f1.x, acc[2]); acc[3] = fmaf(a, f1.y, acc[3]);
        acc[4] = fmaf(a, f2.x, acc[4]); acc[5] = fmaf(a, f2.y, acc[5]);
        acc[6] = fmaf(a, f3.x, acc[6]); acc[7] = fmaf(a, f3.y, acc[7]);
    }

    if (sgrp == 1) {
        #pragma unroll
        for (int j = 0; j < 8; j++) sred[col][j] = acc[j];
    }
    __syncthreads();
    if (sgrp == 0) {
        #pragma unroll
        for (int j = 0; j < 8; j++)
            atomicAdd(&ctx[b * UNITS + col * 8 + j], acc[j] + sred[col][j]);
    }
}

// ------------------------- host launcher ----------------------------------
extern "C" void kernel_launch(void* const* d_in, const int* in_sizes, int n_in,
                              void* d_out, int out_size) {
    const float* s_prev = (const float*)d_in[0];
    const float* hidden = (const float*)d_in[1];
    const float* W_w    = (const float*)d_in[2];
    const float* W_b    = (const float*)d_in[3];
    const float* U_w    = (const float*)d_in[4];
    const float* U_b    = (const float*)d_in[5];
    const float* V_w    = (const float*)d_in[6];
    // d_in[7] = V_b: constant shift of scores, softmax-invariant -> unused.

    float* out_ctx   = (float*)d_out;                  // BATCH*UNITS
    float* out_alpha = (float*)d_out + BATCH * UNITS;  // BATCH*SEQ

    cudaFuncSetAttribute(score_gemm_kernel,
                         cudaFuncAttributeMaxDynamicSharedMemorySize, SMEM_GEMM);

    // 1. fused preprocessing: decoder + U^T cvt + hidden cvt, one launch
    preprocess_kernel<<<PP_DEC + PP_U + PP_HID, 256>>>(
        (const float4*)hidden, U_w, s_prev, W_w, W_b, U_b, out_ctx);
    // 2. fused HMMA GEMM + tanh + V reduction
    score_gemm_kernel<<<dim3(UNITS / 128, MTOT / 128), 128, SMEM_GEMM>>>(V_w);
    // 3. softmax
    softmax_kernel<<<BATCH, 256>>>(out_alpha);
    // 4. context from fp16 hidden (16B loads, s-split 32)
    context16_kernel<<<dim3(BATCH, 32), 256>>>(out_alpha, out_ctx);
}